// round 1
// baseline (speedup 1.0000x reference)
#include <cuda_runtime.h>
#include <math.h>

#define MDIM  128
#define PITCH 129           // float2 row pitch (pad to break bank conflicts)
#define NF    33
#define NPIX  16384
#define NT    512
#define NCOEF 672

__device__ float2 Xf_g[2 * NPIX];           // fft2(x), natural order
__device__ float  out_full_g[2 * NF * NF];  // full (b,i,j) correlation table

__device__ __forceinline__ float2 cmulf(float2 a, float2 b) {
    return make_float2(fmaf(a.x, b.x, -a.y * b.y), fmaf(a.x, b.y, a.y * b.x));
}
__device__ __forceinline__ int rev7(int x) { return (int)(__brev((unsigned)x) >> 25); }

// One 1D FFT sweep over 128 lines of length 128 inside the SMEM tile.
// addr(line, pos) = line*sl + pos*sp.
// DIF: natural in -> bit-reversed out.  DIT: bit-reversed in -> natural out.
// No 1/N scaling applied here.
__device__ void fft_stage_loop(float2* t, const float2* W,
                               int sl, int sp, bool inverse, bool dif, int tid)
{
    if (dif) {
        for (int lm = 7; lm >= 1; --lm) {
            int half = 1 << (lm - 1);
            __syncthreads();
            #pragma unroll 1
            for (int q = tid; q < MDIM * 64; q += NT) {
                int line = q & (MDIM - 1);
                int bf   = q >> 7;
                int p    = bf & (half - 1);
                int g    = bf >> (lm - 1);
                int i1   = (g << lm) + p;
                int i2   = i1 + half;
                float2 a = t[line * sl + i1 * sp];
                float2 b = t[line * sl + i2 * sp];
                float2 w = W[p << (7 - lm)];
                if (inverse) w.y = -w.y;
                float2 d = make_float2(a.x - b.x, a.y - b.y);
                t[line * sl + i1 * sp] = make_float2(a.x + b.x, a.y + b.y);
                t[line * sl + i2 * sp] = cmulf(d, w);
            }
        }
    } else {
        for (int lm = 1; lm <= 7; ++lm) {
            int half = 1 << (lm - 1);
            __syncthreads();
            #pragma unroll 1
            for (int q = tid; q < MDIM * 64; q += NT) {
                int line = q & (MDIM - 1);
                int bf   = q >> 7;
                int p    = bf & (half - 1);
                int g    = bf >> (lm - 1);
                int i1   = (g << lm) + p;
                int i2   = i1 + half;
                float2 a = t[line * sl + i1 * sp];
                float2 b = t[line * sl + i2 * sp];
                float2 w = W[p << (7 - lm)];
                if (inverse) w.y = -w.y;
                float2 wb = cmulf(b, w);
                t[line * sl + i1 * sp] = make_float2(a.x + wb.x, a.y + wb.y);
                t[line * sl + i2 * sp] = make_float2(a.x - wb.x, a.y - wb.y);
            }
        }
    }
    __syncthreads();
}

__device__ __forceinline__ void init_twiddles(float2* Wsh, int tid)
{
    if (tid < 64) {
        float ang = -2.0f * 3.14159265358979323846f * (float)tid / 128.0f;
        float s, c;
        sincosf(ang, &s, &c);
        Wsh[tid] = make_float2(c, s);
    }
    __syncthreads();
}

// Kernel 1: Xf[b] = fft2(x[b]), natural order (2 blocks)
__global__ void __launch_bounds__(NT) fft_x_kernel(const float* __restrict__ x)
{
    extern __shared__ float2 tile[];
    __shared__ float2 Wsh[64];
    int tid = threadIdx.x;
    int b   = blockIdx.x;
    init_twiddles(Wsh, tid);

    for (int q = tid; q < NPIX; q += NT)
        tile[q + (q >> 7)] = make_float2(x[b * NPIX + q], 0.0f);

    // forward DIF along rows then columns -> storage (r,c) holds freq (rev r, rev c)
    fft_stage_loop(tile, Wsh, PITCH, 1, false, true, tid);
    fft_stage_loop(tile, Wsh, 1, PITCH, false, true, tid);

    for (int q = tid; q < NPIX; q += NT) {
        int r = q >> 7, c = q & 127;
        Xf_g[b * NPIX + (rev7(r) << 7) + rev7(c)] = tile[q + (q >> 7)];
    }
}

// Kernel 2: per (b,i) block -> ifft2(F_i*Xf), abs_eps, fft2, fused 33-way reduce
__global__ void __launch_bounds__(NT) scat_kernel(const float* __restrict__ filters)
{
    extern __shared__ float2 tile[];
    __shared__ float2 Wsh[64];
    __shared__ float  wsum[16 * NF];
    int tid = threadIdx.x;
    int blk = blockIdx.x;
    int b   = (blk >= NF) ? 1 : 0;
    int i   = blk - b * NF;
    init_twiddles(Wsh, tid);

    const float2* Xf = &Xf_g[b * NPIX];
    const float*  Fi = &filters[i * NPIX];

    for (int q = tid; q < NPIX; q += NT) {
        float  f = Fi[q];
        float2 z = Xf[q];
        tile[q + (q >> 7)] = make_float2(f * z.x, f * z.y);
    }

    // inverse fft2 (unnormalized): DIF both dims -> spatial, bit-reversed both dims
    fft_stage_loop(tile, Wsh, PITCH, 1, true, true, tid);
    fft_stage_loop(tile, Wsh, 1, PITCH, true, true, tid);

    // abs_eps with the 1/(M*N) ifft normalization applied inside the sqrt
    const float s = 1.0f / 16384.0f;
    for (int q = tid; q < NPIX; q += NT) {
        float2 z = tile[q + (q >> 7)];
        float xr = z.x * s, xi = z.y * s;
        float xa = sqrtf(fmaf(xr, xr, fmaf(xi, xi, 1e-6f)));
        tile[q + (q >> 7)] = make_float2(xa, 0.0f);
    }
    __syncthreads();

    // forward fft2: DIT both dims consumes the bit-reversed layout -> natural freq
    fft_stage_loop(tile, Wsh, 1, PITCH, false, false, tid);
    fft_stage_loop(tile, Wsh, PITCH, 1, false, false, tid);

    // fused reduction: out[b,i,j] = c * sum_k F_j[k]^2 * Re[conj(Xf[k]) * XAf[k]]
    float acc[NF];
    #pragma unroll
    for (int j = 0; j < NF; ++j) acc[j] = 0.0f;

    for (int q = tid; q < NPIX; q += NT) {
        float2 X = Xf[q];
        float2 A = tile[q + (q >> 7)];
        float  g = X.x * A.x + X.y * A.y;
        #pragma unroll
        for (int j = 0; j < NF; ++j) {
            float f = filters[j * NPIX + q];
            acc[j] = fmaf(f * f, g, acc[j]);
        }
    }

    int lane = tid & 31, wid = tid >> 5;
    #pragma unroll
    for (int j = 0; j < NF; ++j) {
        float v = acc[j];
        #pragma unroll
        for (int o = 16; o > 0; o >>= 1) v += __shfl_down_sync(0xffffffffu, v, o);
        if (lane == 0) wsum[wid * NF + j] = v;
    }
    __syncthreads();
    if (tid < NF) {
        float v = 0.0f;
        #pragma unroll
        for (int w = 0; w < 16; ++w) v += wsum[w * NF + tid];
        out_full_g[(b * NF + i) * NF + tid] = v * (1.0f / (16384.0f * 16384.0f));
    }
}

// Kernel 3: gather the 672 (i,j) pairs of indices_third_order(J=4, L=8)
__global__ void gather_kernel(float* __restrict__ out)
{
    int t = threadIdx.x;   // 0..671
    int b = blockIdx.x;    // 0..1
    if (t >= NCOEF) return;

    int j1 = 0, off = 0;
    #pragma unroll
    for (int jj = 0; jj < 4; ++jj) {
        int cc = (4 - jj) * 8 + 1;
        int sz = 8 * cc;
        if (t < off + sz) { j1 = jj; break; }
        off += sz;
    }
    int c  = (4 - j1) * 8 + 1;
    int l1 = (t - off) / c;
    int r  = (t - off) % c;
    int i  = j1 * 8 + l1;
    int j;
    if (r == c - 1) j = 32;                       // lowpass pairing
    else           j = (j1 + r / 8) * 8 + (r % 8);

    out[b * NCOEF + t] = out_full_g[(b * NF + i) * NF + j];
}

extern "C" void kernel_launch(void* const* d_in, const int* in_sizes, int n_in,
                              void* d_out, int out_size)
{
    const float* a0 = (const float*)d_in[0];
    const float* a1 = (const float*)d_in[1];
    // x has 2*1*128*128 = 32768 elems, filters 33*128*128 = 540672
    const float* x       = (in_sizes[0] < in_sizes[1]) ? a0 : a1;
    const float* filters = (in_sizes[0] < in_sizes[1]) ? a1 : a0;

    size_t smem = (size_t)MDIM * PITCH * sizeof(float2);  // 132096 B
    cudaFuncSetAttribute(fft_x_kernel, cudaFuncAttributeMaxDynamicSharedMemorySize, (int)smem);
    cudaFuncSetAttribute(scat_kernel,  cudaFuncAttributeMaxDynamicSharedMemorySize, (int)smem);

    fft_x_kernel<<<2, NT, smem>>>(x);
    scat_kernel<<<2 * NF, NT, smem>>>(filters);
    gather_kernel<<<2, NCOEF>>>((float*)d_out);
}

// round 2
// speedup vs baseline: 1.5958x; 1.5958x over previous
#include <cuda_runtime.h>
#include <math.h>

#define NF     33
#define NPIX   16384
#define NT     512
#define NCOEF  672
#define PITCH  129           // float2 pitch for 128x128 tile
#define NCHUNK 128           // split-K chunks in gemm

__device__ __align__(256) float2 XfTmp_g[2 * NPIX];
__device__ __align__(256) float2 Xf_g[2 * NPIX];       // fft2(x), digit-reversed order
__device__ __align__(256) float  Fperm_g[NF * NPIX];   // filters, digit-reversed
__device__ __align__(256) float  Fsq_g[NF * NPIX];     // filters^2, digit-reversed
__device__ __align__(256) float  G_g[2 * NF * NPIX];   // Re(conj(Xf) * XAf)
__device__ __align__(256) float  partial_g[NCHUNK * 2 * NF * NF];

__device__ __forceinline__ float2 cmulf(float2 a, float2 b) {
    return make_float2(fmaf(a.x, b.x, -a.y * b.y), fmaf(a.x, b.y, a.y * b.x));
}

// inverse of the DIF(4,4,4,2) digit-reversal: storage pos -> natural freq
__device__ __forceinline__ int invp(int s) {
    return (s >> 5) + (((s >> 3) & 3) << 2) + (((s >> 1) & 3) << 4) + ((s & 1) << 6);
}

__device__ __forceinline__ void init_W(float2* W, int tid) {
    if (tid < 128) {
        float s, c;
        sincosf(-2.0f * 3.14159265358979323846f * (float)tid / 128.0f, &s, &c);
        W[tid] = make_float2(c, s);
    }
}

// Radix-4 sweep over nlines lines of a 128-point axis.
// addr(line, pos) = line*sl + pos*sp. DIF: twiddle after DFT; DIT: before.
template<bool INV, bool DIT>
__device__ __forceinline__ void sweep_r4(float2* t, const float2* W,
                                         int log2nl, int sl, int sp,
                                         int log2L, int tid, int nthr)
{
    int nlines = 1 << log2nl;
    int total  = nlines << 5;               // nlines * 32 butterflies
    int lQ = log2L - 2;
    int Qs = (1 << lQ) * sp;
    __syncthreads();
    for (int q = tid; q < total; q += nthr) {
        int line = q & (nlines - 1);
        int bf   = q >> log2nl;
        int p = bf & ((1 << lQ) - 1);
        int g = bf >> lQ;
        int a = line * sl + ((g << log2L) + p) * sp;
        float2 x0 = t[a], x1 = t[a + Qs], x2 = t[a + 2 * Qs], x3 = t[a + 3 * Qs];
        int e = p << (7 - log2L);
        float2 w1 = W[e], w2 = W[2 * e], w3 = W[3 * e];
        if (INV) { w1.y = -w1.y; w2.y = -w2.y; w3.y = -w3.y; }
        if (DIT) { x1 = cmulf(x1, w1); x2 = cmulf(x2, w2); x3 = cmulf(x3, w3); }
        float2 t0 = make_float2(x0.x + x2.x, x0.y + x2.y);
        float2 t1 = make_float2(x0.x - x2.x, x0.y - x2.y);
        float2 t2 = make_float2(x1.x + x3.x, x1.y + x3.y);
        float2 t3 = make_float2(x1.x - x3.x, x1.y - x3.y);
        float2 y0 = make_float2(t0.x + t2.x, t0.y + t2.y);
        float2 y2 = make_float2(t0.x - t2.x, t0.y - t2.y);
        float2 y1, y3;
        if (!INV) { y1 = make_float2(t1.x + t3.y, t1.y - t3.x);
                    y3 = make_float2(t1.x - t3.y, t1.y + t3.x); }
        else      { y1 = make_float2(t1.x - t3.y, t1.y + t3.x);
                    y3 = make_float2(t1.x + t3.y, t1.y - t3.x); }
        if (!DIT) { y1 = cmulf(y1, w1); y2 = cmulf(y2, w2); y3 = cmulf(y3, w3); }
        t[a] = y0; t[a + Qs] = y1; t[a + 2 * Qs] = y2; t[a + 3 * Qs] = y3;
    }
}

// Radix-2 sweep (L=2): no twiddle, identical for DIF/DIT, fwd/inv.
__device__ __forceinline__ void sweep_r2(float2* t, int log2nl, int sl, int sp,
                                         int tid, int nthr)
{
    int nlines = 1 << log2nl;
    int total  = nlines << 6;
    __syncthreads();
    for (int q = tid; q < total; q += nthr) {
        int line = q & (nlines - 1);
        int bf   = q >> log2nl;
        int a = line * sl + (2 * bf) * sp;
        float2 x0 = t[a], x1 = t[a + sp];
        t[a]      = make_float2(x0.x + x1.x, x0.y + x1.y);
        t[a + sp] = make_float2(x0.x - x1.x, x0.y - x1.y);
    }
}

// ---------- kernel: permute filters into digit-reversed order ----------
__global__ void prep_kernel(const float* __restrict__ filters)
{
    int i = blockIdx.x;
    for (int s = threadIdx.x; s < NPIX; s += blockDim.x) {
        int kr = invp(s >> 7), kc = invp(s & 127);
        float f = __ldg(&filters[i * NPIX + kr * 128 + kc]);
        Fperm_g[i * NPIX + s] = f;
        Fsq_g[i * NPIX + s]   = f * f;
    }
}

// ---------- kernel: forward DIF along rows of x ----------
__global__ void __launch_bounds__(NT) fft_rows_kernel(const float* __restrict__ x)
{
    __shared__ float2 W[128];
    __shared__ float2 tile[32 * PITCH];
    int tid = threadIdx.x;
    init_W(W, tid);
    int b = blockIdx.x >> 2, r0 = (blockIdx.x & 3) * 32;
    for (int q = tid; q < 32 * 128; q += NT) {
        int r = q >> 7, c = q & 127;
        tile[r * PITCH + c] = make_float2(x[b * NPIX + (r0 + r) * 128 + c], 0.0f);
    }
    sweep_r4<false,false>(tile, W, 5, PITCH, 1, 7, tid, NT);
    sweep_r4<false,false>(tile, W, 5, PITCH, 1, 5, tid, NT);
    sweep_r4<false,false>(tile, W, 5, PITCH, 1, 3, tid, NT);
    sweep_r2(tile, 5, PITCH, 1, tid, NT);
    __syncthreads();
    for (int q = tid; q < 32 * 128; q += NT) {
        int r = q >> 7, c = q & 127;
        XfTmp_g[b * NPIX + (r0 + r) * 128 + c] = tile[r * PITCH + c];
    }
}

// ---------- kernel: forward DIF along columns ----------
__global__ void __launch_bounds__(NT) fft_cols_kernel()
{
    __shared__ float2 W[128];
    __shared__ float2 tile[128 * 33];
    int tid = threadIdx.x;
    init_W(W, tid);
    int b = blockIdx.x >> 2, c0 = (blockIdx.x & 3) * 32;
    for (int q = tid; q < 128 * 32; q += NT) {
        int pos = q >> 5, col = q & 31;
        tile[pos * 33 + col] = XfTmp_g[b * NPIX + pos * 128 + c0 + col];
    }
    sweep_r4<false,false>(tile, W, 5, 1, 33, 7, tid, NT);
    sweep_r4<false,false>(tile, W, 5, 1, 33, 5, tid, NT);
    sweep_r4<false,false>(tile, W, 5, 1, 33, 3, tid, NT);
    sweep_r2(tile, 5, 1, 33, tid, NT);
    __syncthreads();
    for (int q = tid; q < 128 * 32; q += NT) {
        int pos = q >> 5, col = q & 31;
        Xf_g[b * NPIX + pos * 128 + c0 + col] = tile[pos * 33 + col];
    }
}

// ---------- kernel: per (b,i): ifft2(F_i*Xf) -> abs_eps -> fft2 -> G ----------
__global__ void __launch_bounds__(NT) scat_kernel()
{
    extern __shared__ float2 tile[];   // 128 * PITCH
    __shared__ float2 W[128];
    int tid = threadIdx.x;
    init_W(W, tid);
    int blk = blockIdx.x;
    int b = (blk >= NF) ? 1 : 0;
    int i = blk - b * NF;
    const float2* Xf = Xf_g + b * NPIX;
    const float*  Fp = Fperm_g + i * NPIX;

    // inverse-DIT rows, stage L=2 fused with the global load + filter multiply
    __syncthreads();
    for (int q = tid; q < 8192; q += NT) {
        int line = q >> 6;          // row
        int bf   = q & 63;
        int c0 = 2 * bf;
        int q0 = line * 128 + c0;
        float4 Xp = *(const float4*)&Xf[q0];       // Xf[q0], Xf[q0+1]
        float2 fp = *(const float2*)&Fp[q0];
        float2 a0 = make_float2(fp.x * Xp.x, fp.x * Xp.y);
        float2 a1 = make_float2(fp.y * Xp.z, fp.y * Xp.w);
        tile[line * PITCH + c0]     = make_float2(a0.x + a1.x, a0.y + a1.y);
        tile[line * PITCH + c0 + 1] = make_float2(a0.x - a1.x, a0.y - a1.y);
    }
    sweep_r4<true,true>(tile, W, 7, PITCH, 1, 3, tid, NT);
    sweep_r4<true,true>(tile, W, 7, PITCH, 1, 5, tid, NT);
    sweep_r4<true,true>(tile, W, 7, PITCH, 1, 7, tid, NT);
    // inverse-DIT cols
    sweep_r2(tile, 7, 1, PITCH, tid, NT);
    sweep_r4<true,true>(tile, W, 7, 1, PITCH, 3, tid, NT);
    sweep_r4<true,true>(tile, W, 7, 1, PITCH, 5, tid, NT);
    // last col stage (L=128) fused with abs_eps (+ ifft 1/16384 normalization)
    {
        const float s = 1.0f / 16384.0f;
        __syncthreads();
        for (int q = tid; q < 4096; q += NT) {
            int line = q & 127;
            int p    = q >> 7;                  // Q=32, single group
            int a = line + p * PITCH;
            float2 x0 = tile[a], x1 = tile[a + 32 * PITCH],
                   x2 = tile[a + 64 * PITCH], x3 = tile[a + 96 * PITCH];
            float2 w1 = W[p], w2 = W[2 * p], w3 = W[3 * p];
            w1.y = -w1.y; w2.y = -w2.y; w3.y = -w3.y;   // inverse
            x1 = cmulf(x1, w1); x2 = cmulf(x2, w2); x3 = cmulf(x3, w3);  // DIT
            float2 t0 = make_float2(x0.x + x2.x, x0.y + x2.y);
            float2 t1 = make_float2(x0.x - x2.x, x0.y - x2.y);
            float2 t2 = make_float2(x1.x + x3.x, x1.y + x3.y);
            float2 t3 = make_float2(x1.x - x3.x, x1.y - x3.y);
            float2 y0 = make_float2(t0.x + t2.x, t0.y + t2.y);
            float2 y2 = make_float2(t0.x - t2.x, t0.y - t2.y);
            float2 y1 = make_float2(t1.x - t3.y, t1.y + t3.x);
            float2 y3 = make_float2(t1.x + t3.y, t1.y - t3.x);
            float2 ys[4] = {y0, y1, y2, y3};
            #pragma unroll
            for (int m = 0; m < 4; ++m) {
                float xr = ys[m].x * s, xi = ys[m].y * s;
                tile[a + m * 32 * PITCH] =
                    make_float2(sqrtf(fmaf(xr, xr, fmaf(xi, xi, 1e-6f))), 0.0f);
            }
        }
    }
    // forward-DIF rows
    sweep_r4<false,false>(tile, W, 7, PITCH, 1, 7, tid, NT);
    sweep_r4<false,false>(tile, W, 7, PITCH, 1, 5, tid, NT);
    sweep_r4<false,false>(tile, W, 7, PITCH, 1, 3, tid, NT);
    sweep_r2(tile, 7, PITCH, 1, tid, NT);
    // forward-DIF cols; final L=2 stage fused with G output
    sweep_r4<false,false>(tile, W, 7, 1, PITCH, 7, tid, NT);
    sweep_r4<false,false>(tile, W, 7, 1, PITCH, 5, tid, NT);
    sweep_r4<false,false>(tile, W, 7, 1, PITCH, 3, tid, NT);
    __syncthreads();
    {
        float* G = G_g + (b * NF + i) * NPIX;
        for (int q = tid; q < 8192; q += NT) {
            int line = q & 127;                 // column
            int bf   = q >> 7;
            int r0 = 2 * bf;
            float2 x0 = tile[line + r0 * PITCH];
            float2 x1 = tile[line + (r0 + 1) * PITCH];
            float2 y0 = make_float2(x0.x + x1.x, x0.y + x1.y);
            float2 y1 = make_float2(x0.x - x1.x, x0.y - x1.y);
            int q0 = r0 * 128 + line, q1 = q0 + 128;
            float2 X0 = Xf[q0], X1 = Xf[q1];
            G[q0] = X0.x * y0.x + X0.y * y0.y;
            G[q1] = X1.x * y1.x + X1.y * y1.y;
        }
    }
}

// ---------- kernel: split-K GEMM  C[66,33] += G[66,chunk] * Fsq[33,chunk]^T ----------
__global__ void __launch_bounds__(256) gemm_kernel()
{
    __shared__ float fs[NF * 132];
    int tid = threadIdx.x, lane = tid & 31, w = tid >> 5;
    int k0 = blockIdx.x * 128;
    for (int idx = tid; idx < NF * 128; idx += 256) {
        int j = idx >> 7, px = idx & 127;
        fs[j * 132 + px] = Fsq_g[j * NPIX + k0 + px];
    }
    __syncthreads();
    for (int grp = w; grp < 17; grp += 8) {
        int r0 = grp * 4;
        int nr = (66 - r0 < 4) ? (66 - r0) : 4;
        float acc[4] = {0.f, 0.f, 0.f, 0.f};
        const float4* fsp = (const float4*)&fs[lane * 132];   // j = lane
        for (int px4 = 0; px4 < 32; ++px4) {
            float4 f = fsp[px4];
            #pragma unroll
            for (int u = 0; u < 4; ++u) {
                if (u < nr) {
                    float4 g = *(const float4*)&G_g[(r0 + u) * NPIX + k0 + px4 * 4];
                    acc[u] += g.x * f.x + g.y * f.y + g.z * f.z + g.w * f.w;
                }
            }
        }
        #pragma unroll
        for (int u = 0; u < 4; ++u)
            if (u < nr)
                partial_g[(blockIdx.x * 66 + r0 + u) * NF + lane] = acc[u];
        // j = 32 (lowpass), warp-cooperative
        for (int u = 0; u < nr; ++u) {
            float a = 0.f;
            #pragma unroll
            for (int v = 0; v < 4; ++v) {
                int px = lane + 32 * v;
                a += G_g[(r0 + u) * NPIX + k0 + px] * fs[32 * 132 + px];
            }
            #pragma unroll
            for (int o = 16; o > 0; o >>= 1) a += __shfl_down_sync(0xffffffffu, a, o);
            if (lane == 0)
                partial_g[(blockIdx.x * 66 + r0 + u) * NF + 32] = a;
        }
    }
}

// ---------- kernel: sum partials + gather the 672 (i,j) pairs ----------
__global__ void gather_kernel(float* __restrict__ out)
{
    int gt = blockIdx.x * 64 + threadIdx.x;
    if (gt >= 2 * NCOEF) return;
    int b = gt / NCOEF, t = gt % NCOEF;

    int j1 = 0, off = 0;
    #pragma unroll
    for (int jj = 0; jj < 4; ++jj) {
        int sz = 8 * ((4 - jj) * 8 + 1);
        if (t < off + sz) { j1 = jj; break; }
        off += sz;
    }
    int c  = (4 - j1) * 8 + 1;
    int l1 = (t - off) / c;
    int r  = (t - off) % c;
    int i  = j1 * 8 + l1;
    int j  = (r == c - 1) ? 32 : (j1 + r / 8) * 8 + (r % 8);

    int idx = (b * NF + i) * NF + j;
    float v0 = 0.f, v1 = 0.f, v2 = 0.f, v3 = 0.f;
    #pragma unroll 4
    for (int ch = 0; ch < NCHUNK; ch += 4) {
        v0 += partial_g[(ch + 0) * (2 * NF * NF) + idx];
        v1 += partial_g[(ch + 1) * (2 * NF * NF) + idx];
        v2 += partial_g[(ch + 2) * (2 * NF * NF) + idx];
        v3 += partial_g[(ch + 3) * (2 * NF * NF) + idx];
    }
    out[gt] = (v0 + v1 + v2 + v3) * (1.0f / (16384.0f * 16384.0f));
}

extern "C" void kernel_launch(void* const* d_in, const int* in_sizes, int n_in,
                              void* d_out, int out_size)
{
    const float* a0 = (const float*)d_in[0];
    const float* a1 = (const float*)d_in[1];
    const float* x       = (in_sizes[0] < in_sizes[1]) ? a0 : a1;
    const float* filters = (in_sizes[0] < in_sizes[1]) ? a1 : a0;

    size_t smem = (size_t)128 * PITCH * sizeof(float2);   // 132096 B
    cudaFuncSetAttribute(scat_kernel, cudaFuncAttributeMaxDynamicSharedMemorySize, (int)smem);

    prep_kernel<<<NF, 256>>>(filters);
    fft_rows_kernel<<<8, NT>>>(x);
    fft_cols_kernel<<<8, NT>>>();
    scat_kernel<<<2 * NF, NT, smem>>>();
    gemm_kernel<<<NCHUNK, 256>>>();
    gather_kernel<<<(2 * NCOEF + 63) / 64, 64>>>((float*)d_out);
}

// round 3
// speedup vs baseline: 1.7999x; 1.1279x over previous
#include <cuda_runtime.h>
#include <math.h>

#define NF     33
#define NPIX   16384
#define NTS    1024          // scat threads
#define NCOEF  672
#define PITCH  129           // float2 pitch for 128x128 tile
#define NCHUNK 128           // split-K chunks in gemm

__device__ __align__(256) float2 XfTmp_g[2 * NPIX];
__device__ __align__(256) float2 Xf_g[2 * NPIX];       // fft2(x), digit-reversed order
__device__ __align__(256) float  Fperm_g[NF * NPIX];   // filters, digit-reversed
__device__ __align__(256) float  Fsq_g[NF * NPIX];     // filters^2, digit-reversed
__device__ __align__(256) float  G_g[2 * NF * NPIX];   // Re(conj(Xf) * XAf)
__device__ __align__(256) float  partial_g[NCHUNK * 2 * NF * NF];

__device__ __forceinline__ float2 cmulf(float2 a, float2 b) {
    return make_float2(fmaf(a.x, b.x, -a.y * b.y), fmaf(a.x, b.y, a.y * b.x));
}

// inverse of the DIF(4,4,4,2) digit-reversal: storage pos -> natural freq
__device__ __forceinline__ int invp(int s) {
    return (s >> 5) + (((s >> 3) & 3) << 2) + (((s >> 1) & 3) << 4) + ((s & 1) << 6);
}

__device__ __forceinline__ void init_W(float2* W, int tid) {
    if (tid < 128) {
        float s, c;
        sincosf(-2.0f * 3.14159265358979323846f * (float)tid / 128.0f, &s, &c);
        W[tid] = make_float2(c, s);
    }
}

// Radix-4 sweep over nlines lines of a 128-point axis.
// addr(line, pos) = line*sl + pos*sp. DIF: twiddle after DFT; DIT: before.
template<bool INV, bool DIT>
__device__ __forceinline__ void sweep_r4(float2* t, const float2* W,
                                         int log2nl, int sl, int sp,
                                         int log2L, int tid, int nthr)
{
    int nlines = 1 << log2nl;
    int total  = nlines << 5;               // nlines * 32 butterflies
    int lQ = log2L - 2;
    int Qs = (1 << lQ) * sp;
    __syncthreads();
    for (int q = tid; q < total; q += nthr) {
        int line = q & (nlines - 1);
        int bf   = q >> log2nl;
        int p = bf & ((1 << lQ) - 1);
        int g = bf >> lQ;
        int a = line * sl + ((g << log2L) + p) * sp;
        float2 x0 = t[a], x1 = t[a + Qs], x2 = t[a + 2 * Qs], x3 = t[a + 3 * Qs];
        int e = p << (7 - log2L);
        float2 w1 = W[e], w2 = W[2 * e], w3 = W[3 * e];
        if (INV) { w1.y = -w1.y; w2.y = -w2.y; w3.y = -w3.y; }
        if (DIT) { x1 = cmulf(x1, w1); x2 = cmulf(x2, w2); x3 = cmulf(x3, w3); }
        float2 t0 = make_float2(x0.x + x2.x, x0.y + x2.y);
        float2 t1 = make_float2(x0.x - x2.x, x0.y - x2.y);
        float2 t2 = make_float2(x1.x + x3.x, x1.y + x3.y);
        float2 t3 = make_float2(x1.x - x3.x, x1.y - x3.y);
        float2 y0 = make_float2(t0.x + t2.x, t0.y + t2.y);
        float2 y2 = make_float2(t0.x - t2.x, t0.y - t2.y);
        float2 y1, y3;
        if (!INV) { y1 = make_float2(t1.x + t3.y, t1.y - t3.x);
                    y3 = make_float2(t1.x - t3.y, t1.y + t3.x); }
        else      { y1 = make_float2(t1.x - t3.y, t1.y + t3.x);
                    y3 = make_float2(t1.x + t3.y, t1.y - t3.x); }
        if (!DIT) { y1 = cmulf(y1, w1); y2 = cmulf(y2, w2); y3 = cmulf(y3, w3); }
        t[a] = y0; t[a + Qs] = y1; t[a + 2 * Qs] = y2; t[a + 3 * Qs] = y3;
    }
}

// Radix-2 sweep (L=2): no twiddle, identical for DIF/DIT, fwd/inv.
__device__ __forceinline__ void sweep_r2(float2* t, int log2nl, int sl, int sp,
                                         int tid, int nthr)
{
    int nlines = 1 << log2nl;
    int total  = nlines << 6;
    __syncthreads();
    for (int q = tid; q < total; q += nthr) {
        int line = q & (nlines - 1);
        int bf   = q >> log2nl;
        int a = line * sl + (2 * bf) * sp;
        float2 x0 = t[a], x1 = t[a + sp];
        t[a]      = make_float2(x0.x + x1.x, x0.y + x1.y);
        t[a + sp] = make_float2(x0.x - x1.x, x0.y - x1.y);
    }
}

// ---------- kernel: permute filters into digit-reversed order ----------
__global__ void __launch_bounds__(512) prep_kernel(const float* __restrict__ filters)
{
    int i = blockIdx.x >> 1;
    int s0 = (blockIdx.x & 1) * 8192;
    for (int q = threadIdx.x; q < 8192; q += 512) {
        int s = s0 + q;
        int kr = invp(s >> 7), kc = invp(s & 127);
        float f = __ldg(&filters[i * NPIX + kr * 128 + kc]);
        Fperm_g[i * NPIX + s] = f;
        Fsq_g[i * NPIX + s]   = f * f;
    }
}

// ---------- kernel: forward DIF along rows of x ----------
__global__ void __launch_bounds__(256) fft_rows_kernel(const float* __restrict__ x)
{
    __shared__ float2 W[128];
    __shared__ float2 tile[16 * PITCH];
    int tid = threadIdx.x;
    init_W(W, tid);
    int b = blockIdx.x >> 3, r0 = (blockIdx.x & 7) * 16;
    for (int q = tid; q < 16 * 128; q += 256) {
        int r = q >> 7, c = q & 127;
        tile[r * PITCH + c] = make_float2(x[b * NPIX + (r0 + r) * 128 + c], 0.0f);
    }
    sweep_r4<false,false>(tile, W, 4, PITCH, 1, 7, tid, 256);
    sweep_r4<false,false>(tile, W, 4, PITCH, 1, 5, tid, 256);
    sweep_r4<false,false>(tile, W, 4, PITCH, 1, 3, tid, 256);
    sweep_r2(tile, 4, PITCH, 1, tid, 256);
    __syncthreads();
    for (int q = tid; q < 16 * 128; q += 256) {
        int r = q >> 7, c = q & 127;
        XfTmp_g[b * NPIX + (r0 + r) * 128 + c] = tile[r * PITCH + c];
    }
}

// ---------- kernel: forward DIF along columns ----------
__global__ void __launch_bounds__(256) fft_cols_kernel()
{
    __shared__ float2 W[128];
    __shared__ float2 tile[128 * 17];
    int tid = threadIdx.x;
    init_W(W, tid);
    int b = blockIdx.x >> 3, c0 = (blockIdx.x & 7) * 16;
    for (int q = tid; q < 128 * 16; q += 256) {
        int pos = q >> 4, col = q & 15;
        tile[pos * 17 + col] = XfTmp_g[b * NPIX + pos * 128 + c0 + col];
    }
    sweep_r4<false,false>(tile, W, 4, 1, 17, 7, tid, 256);
    sweep_r4<false,false>(tile, W, 4, 1, 17, 5, tid, 256);
    sweep_r4<false,false>(tile, W, 4, 1, 17, 3, tid, 256);
    sweep_r2(tile, 4, 1, 17, tid, 256);
    __syncthreads();
    for (int q = tid; q < 128 * 16; q += 256) {
        int pos = q >> 4, col = q & 15;
        Xf_g[b * NPIX + pos * 128 + c0 + col] = tile[pos * 17 + col];
    }
}

// ---------- kernel: per (b,i): ifft2(F_i*Xf) -> abs_eps -> fft2 -> G ----------
__global__ void __launch_bounds__(NTS) scat_kernel()
{
    extern __shared__ float2 tile[];   // 128 * PITCH
    __shared__ float2 W[128];
    int tid = threadIdx.x;
    init_W(W, tid);
    int blk = blockIdx.x;
    int b = (blk >= NF) ? 1 : 0;
    int i = blk - b * NF;
    const float2* Xf = Xf_g + b * NPIX;
    const float*  Fp = Fperm_g + i * NPIX;

    // inverse-DIT rows, stage L=2 fused with the global load + filter multiply
    __syncthreads();
    for (int q = tid; q < 8192; q += NTS) {
        int line = q >> 6;          // row
        int bf   = q & 63;
        int c0 = 2 * bf;
        int q0 = line * 128 + c0;
        float4 Xp = *(const float4*)&Xf[q0];       // Xf[q0], Xf[q0+1]
        float2 fp = *(const float2*)&Fp[q0];
        float2 a0 = make_float2(fp.x * Xp.x, fp.x * Xp.y);
        float2 a1 = make_float2(fp.y * Xp.z, fp.y * Xp.w);
        tile[line * PITCH + c0]     = make_float2(a0.x + a1.x, a0.y + a1.y);
        tile[line * PITCH + c0 + 1] = make_float2(a0.x - a1.x, a0.y - a1.y);
    }
    sweep_r4<true,true>(tile, W, 7, PITCH, 1, 3, tid, NTS);
    sweep_r4<true,true>(tile, W, 7, PITCH, 1, 5, tid, NTS);
    sweep_r4<true,true>(tile, W, 7, PITCH, 1, 7, tid, NTS);
    // inverse-DIT cols
    sweep_r2(tile, 7, 1, PITCH, tid, NTS);
    sweep_r4<true,true>(tile, W, 7, 1, PITCH, 3, tid, NTS);
    sweep_r4<true,true>(tile, W, 7, 1, PITCH, 5, tid, NTS);
    // last col stage (L=128) fused with abs_eps (+ ifft 1/16384 normalization)
    {
        const float s = 1.0f / 16384.0f;
        __syncthreads();
        for (int q = tid; q < 4096; q += NTS) {
            int line = q & 127;
            int p    = q >> 7;                  // Q=32, single group
            int a = line + p * PITCH;
            float2 x0 = tile[a], x1 = tile[a + 32 * PITCH],
                   x2 = tile[a + 64 * PITCH], x3 = tile[a + 96 * PITCH];
            float2 w1 = W[p], w2 = W[2 * p], w3 = W[3 * p];
            w1.y = -w1.y; w2.y = -w2.y; w3.y = -w3.y;   // inverse
            x1 = cmulf(x1, w1); x2 = cmulf(x2, w2); x3 = cmulf(x3, w3);  // DIT
            float2 t0 = make_float2(x0.x + x2.x, x0.y + x2.y);
            float2 t1 = make_float2(x0.x - x2.x, x0.y - x2.y);
            float2 t2 = make_float2(x1.x + x3.x, x1.y + x3.y);
            float2 t3 = make_float2(x1.x - x3.x, x1.y - x3.y);
            float2 y0 = make_float2(t0.x + t2.x, t0.y + t2.y);
            float2 y2 = make_float2(t0.x - t2.x, t0.y - t2.y);
            float2 y1 = make_float2(t1.x - t3.y, t1.y + t3.x);
            float2 y3 = make_float2(t1.x + t3.y, t1.y - t3.x);
            float2 ys[4] = {y0, y1, y2, y3};
            #pragma unroll
            for (int m = 0; m < 4; ++m) {
                float xr = ys[m].x * s, xi = ys[m].y * s;
                tile[a + m * 32 * PITCH] =
                    make_float2(sqrtf(fmaf(xr, xr, fmaf(xi, xi, 1e-6f))), 0.0f);
            }
        }
    }
    // forward-DIF rows
    sweep_r4<false,false>(tile, W, 7, PITCH, 1, 7, tid, NTS);
    sweep_r4<false,false>(tile, W, 7, PITCH, 1, 5, tid, NTS);
    sweep_r4<false,false>(tile, W, 7, PITCH, 1, 3, tid, NTS);
    sweep_r2(tile, 7, PITCH, 1, tid, NTS);
    // forward-DIF cols; final L=2 stage fused with G output
    sweep_r4<false,false>(tile, W, 7, 1, PITCH, 7, tid, NTS);
    sweep_r4<false,false>(tile, W, 7, 1, PITCH, 5, tid, NTS);
    sweep_r4<false,false>(tile, W, 7, 1, PITCH, 3, tid, NTS);
    __syncthreads();
    {
        float* G = G_g + (b * NF + i) * NPIX;
        for (int q = tid; q < 8192; q += NTS) {
            int line = q & 127;                 // column
            int bf   = q >> 7;
            int r0 = 2 * bf;
            float2 x0 = tile[line + r0 * PITCH];
            float2 x1 = tile[line + (r0 + 1) * PITCH];
            float2 y0 = make_float2(x0.x + x1.x, x0.y + x1.y);
            float2 y1 = make_float2(x0.x - x1.x, x0.y - x1.y);
            int q0 = r0 * 128 + line, q1 = q0 + 128;
            float2 X0 = Xf[q0], X1 = Xf[q1];
            G[q0] = X0.x * y0.x + X0.y * y0.y;
            G[q1] = X1.x * y1.x + X1.y * y1.y;
        }
    }
}

// ---------- kernel: split-K GEMM  C[66,33] += G[66,chunk] * Fsq[33,chunk]^T ----------
__global__ void __launch_bounds__(256) gemm_kernel()
{
    __shared__ float fs[NF * 132];
    int tid = threadIdx.x, lane = tid & 31, w = tid >> 5;
    int k0 = blockIdx.x * 128;
    for (int idx = tid; idx < NF * 128; idx += 256) {
        int j = idx >> 7, px = idx & 127;
        fs[j * 132 + px] = Fsq_g[j * NPIX + k0 + px];
    }
    __syncthreads();
    for (int grp = w; grp < 17; grp += 8) {
        int r0 = grp * 4;
        int nr = (66 - r0 < 4) ? (66 - r0) : 4;
        float acc[4] = {0.f, 0.f, 0.f, 0.f};
        const float4* fsp = (const float4*)&fs[lane * 132];   // j = lane
        for (int px4 = 0; px4 < 32; ++px4) {
            float4 f = fsp[px4];
            #pragma unroll
            for (int u = 0; u < 4; ++u) {
                if (u < nr) {
                    float4 g = *(const float4*)&G_g[(r0 + u) * NPIX + k0 + px4 * 4];
                    acc[u] += g.x * f.x + g.y * f.y + g.z * f.z + g.w * f.w;
                }
            }
        }
        #pragma unroll
        for (int u = 0; u < 4; ++u)
            if (u < nr)
                partial_g[(blockIdx.x * 66 + r0 + u) * NF + lane] = acc[u];
        // j = 32 (lowpass), warp-cooperative
        for (int u = 0; u < nr; ++u) {
            float a = 0.f;
            #pragma unroll
            for (int v = 0; v < 4; ++v) {
                int px = lane + 32 * v;
                a += G_g[(r0 + u) * NPIX + k0 + px] * fs[32 * 132 + px];
            }
            #pragma unroll
            for (int o = 16; o > 0; o >>= 1) a += __shfl_down_sync(0xffffffffu, a, o);
            if (lane == 0)
                partial_g[(blockIdx.x * 66 + r0 + u) * NF + 32] = a;
        }
    }
}

// ---------- kernel: sum partials + gather the 672 (i,j) pairs ----------
__global__ void __launch_bounds__(128) gather_kernel(float* __restrict__ out)
{
    int gt = blockIdx.x * 128 + threadIdx.x;
    if (gt >= 2 * NCOEF) return;
    int b = gt / NCOEF, t = gt % NCOEF;

    int j1 = 0, off = 0;
    #pragma unroll
    for (int jj = 0; jj < 4; ++jj) {
        int sz = 8 * ((4 - jj) * 8 + 1);
        if (t < off + sz) { j1 = jj; break; }
        off += sz;
    }
    int c  = (4 - j1) * 8 + 1;
    int l1 = (t - off) / c;
    int r  = (t - off) % c;
    int i  = j1 * 8 + l1;
    int j  = (r == c - 1) ? 32 : (j1 + r / 8) * 8 + (r % 8);

    int idx = (b * NF + i) * NF + j;
    float v0 = 0.f, v1 = 0.f, v2 = 0.f, v3 = 0.f;
    #pragma unroll 8
    for (int ch = 0; ch < NCHUNK; ch += 4) {
        v0 += partial_g[(ch + 0) * (2 * NF * NF) + idx];
        v1 += partial_g[(ch + 1) * (2 * NF * NF) + idx];
        v2 += partial_g[(ch + 2) * (2 * NF * NF) + idx];
        v3 += partial_g[(ch + 3) * (2 * NF * NF) + idx];
    }
    out[gt] = (v0 + v1 + v2 + v3) * (1.0f / (16384.0f * 16384.0f));
}

extern "C" void kernel_launch(void* const* d_in, const int* in_sizes, int n_in,
                              void* d_out, int out_size)
{
    const float* a0 = (const float*)d_in[0];
    const float* a1 = (const float*)d_in[1];
    const float* x       = (in_sizes[0] < in_sizes[1]) ? a0 : a1;
    const float* filters = (in_sizes[0] < in_sizes[1]) ? a1 : a0;

    size_t smem = (size_t)128 * PITCH * sizeof(float2);   // 132096 B
    cudaFuncSetAttribute(scat_kernel, cudaFuncAttributeMaxDynamicSharedMemorySize, (int)smem);

    prep_kernel<<<2 * NF, 512>>>(filters);
    fft_rows_kernel<<<16, 256>>>(x);
    fft_cols_kernel<<<16, 256>>>();
    scat_kernel<<<2 * NF, NTS, smem>>>();
    gemm_kernel<<<NCHUNK, 256>>>();
    gather_kernel<<<(2 * NCOEF + 127) / 128, 128>>>((float*)d_out);
}